// round 13
// baseline (speedup 1.0000x reference)
#include <cuda_runtime.h>
#include <cuda_bf16.h>
#include <cstdint>

typedef unsigned int u32;
typedef unsigned long long u64;

#define VN 48
#define VNN 2304
#define VNNN 110592
#define NB 8
#define SP_EPS 1e-5f
#define PD 50
#define PDD 2500
#define PDDD 125000
#define XOFF 128

// conv1
#define NTILE1 5
#define MT1 500
#define AROWS1 620
#define ASTRIDE1 144
// conv2
#define NTILE2 10
#define MT2 250
#define AROWS2 360
#define ASTRIDE2 272

// ---------------- device scratch ----------------
__device__ float g_xf [((size_t)NB * PDDD + 2 * XOFF) * 32];
__device__ float g_af [((size_t)NB * PDDD + 2 * XOFF) * 64];
__device__ float g_w1f[4 * 9 * 6144];      // conv1: per (cls, kd*3+kh): 64n x 96k
__device__ float g_w2f[4 * 9 * 12288];     // conv2: per (cls, kd*3+kh): 64n x 192k
__device__ float g_mu[NB * 32];
__device__ float g_rsig[NB * 32];

// ---------------- helpers ----------------
__device__ __forceinline__ u32 smem_u32(const void* p) {
    u32 a; asm("{ .reg .u64 t; cvta.to.shared.u64 t, %1; cvt.u32.u64 %0, t; }"
               : "=r"(a) : "l"(p));
    return a;
}
__device__ __forceinline__ void cp16f(u32 dst, const void* src) {
    asm volatile("cp.async.ca.shared.global [%0], [%1], 16;" :: "r"(dst), "l"(src));
}
__device__ __forceinline__ void cp_commit() { asm volatile("cp.async.commit_group;"); }
__device__ __forceinline__ void cp_wait0()  { asm volatile("cp.async.wait_group 0;" ::: "memory"); }
__device__ __forceinline__ u32 tf32r(float v) {
    u32 r; asm("cvt.rna.tf32.f32 %0, %1;" : "=r"(r) : "f"(v)); return r;
}
__device__ __forceinline__ void lds32(u32& r, u32 addr) {
    asm volatile("ld.shared.b32 %0, [%1];" : "=r"(r) : "r"(addr));
}
__device__ __forceinline__ void lds64(u32& r0, u32& r1, u32 addr) {
    asm volatile("ld.shared.v2.b32 {%0,%1}, [%2];" : "=r"(r0), "=r"(r1) : "r"(addr));
}
__device__ __forceinline__ void mmatf32(float* d, const u32* a, u32 b0, u32 b1) {
    asm volatile("mma.sync.aligned.m16n8k8.row.col.f32.tf32.tf32.f32 "
        "{%0,%1,%2,%3}, {%4,%5,%6,%7}, {%8,%9}, {%0,%1,%2,%3};"
        : "+f"(d[0]), "+f"(d[1]), "+f"(d[2]), "+f"(d[3])
        : "r"(a[0]), "r"(a[1]), "r"(a[2]), "r"(a[3]), "r"(b0), "r"(b1));
}

// ---------------------------------------------------------------------------
// stats
// ---------------------------------------------------------------------------
__global__ void stats_kernel(const float* __restrict__ x) {
    int bc = blockIdx.x;
    const float4* xp = reinterpret_cast<const float4*>(x + (size_t)bc * VNNN);
    float s = 0.f, ss = 0.f;
    for (int i = threadIdx.x; i < VNNN / 4; i += blockDim.x) {
        float4 v = xp[i];
        s  += v.x + v.y + v.z + v.w;
        ss += v.x*v.x + v.y*v.y + v.z*v.z + v.w*v.w;
    }
    __shared__ float sh_s[8], sh_ss[8];
    #pragma unroll
    for (int o = 16; o; o >>= 1) {
        s  += __shfl_down_sync(0xffffffffu, s, o);
        ss += __shfl_down_sync(0xffffffffu, ss, o);
    }
    int w = threadIdx.x >> 5, l = threadIdx.x & 31;
    if (l == 0) { sh_s[w] = s; sh_ss[w] = ss; }
    __syncthreads();
    if (w == 0) {
        s  = (l < 8) ? sh_s[l]  : 0.f;
        ss = (l < 8) ? sh_ss[l] : 0.f;
        #pragma unroll
        for (int o = 4; o; o >>= 1) {
            s  += __shfl_down_sync(0xffffffffu, s, o);
            ss += __shfl_down_sync(0xffffffffu, ss, o);
        }
        if (l == 0) {
            float mu  = s / (float)VNNN;
            float var = ss / (float)VNNN - mu * mu;
            g_mu[bc] = mu; g_rsig[bc] = rsqrtf(var + SP_EPS);
        }
    }
}

// ---------------------------------------------------------------------------
// xpose + zero g_af halo (merged)
// ---------------------------------------------------------------------------
__global__ __launch_bounds__(256)
void xpose_kernel(const float* __restrict__ x) {
    int pz = blockIdx.x, b = blockIdx.y;
    for (int c = threadIdx.x; c < PDD; c += 256) {
        int py = c / PD, px = c - py * PD;
        size_t lin = (size_t)XOFF + (size_t)b*PDDD + (size_t)pz*PDD + py*PD + px;
        float4* d = (float4*)(g_xf + lin * 32);
        bool inside = (pz >= 1 && pz <= 48 && py >= 1 && py <= 48 && px >= 1 && px <= 48);
        if (inside) {
            const float* xb = x + (size_t)b*32*VNNN + (size_t)(pz-1)*VNN + (py-1)*VN + (px-1);
            u32 p[32];
            #pragma unroll
            for (int q = 0; q < 32; q++) p[q] = tf32r(xb[(size_t)q * VNNN]);
            #pragma unroll
            for (int i = 0; i < 8; i++) d[i] = ((float4*)p)[i];
        } else {
            float4 z = make_float4(0.f,0.f,0.f,0.f);
            #pragma unroll
            for (int i = 0; i < 8; i++) d[i] = z;
            float4* da = (float4*)(g_af + lin * 64);
            #pragma unroll
            for (int i = 0; i < 16; i++) da[i] = z;
        }
    }
}

// ---------------------------------------------------------------------------
// Pre-arranged tf32 B tiles, folded-kw groups, lane-major pair layout
// ---------------------------------------------------------------------------
__global__ void prepb_kernel(const float* __restrict__ Ws,
                             const float* __restrict__ Wg,
                             const float* __restrict__ Wb) {
    int t = blockIdx.x;                 // 0..26
    int cls = blockIdx.y & 3;
    int which = blockIdx.y >> 2;
    if (which == 0) {
        // conv1: 9 groups x 6144 entries, processed as 27 blocks x 2048
        for (int i = threadIdx.x; i < 2048; i += 256) {
            int gi = t * 2048 + i;
            int grp = gi / 6144;
            int r   = gi - grp * 6144;
            int n = r / 96, k = r - n * 96;
            int kw = k >> 5, cch = k & 31;
            int tap = grp * 3 + kw;
            float w = Ws[((size_t)(cls*64 + n)*32 + cch)*27 + tap];
            u32 tv = tf32r(w);
            int ks = k >> 3, kc = k & 7, c4 = kc & 3, p = kc >> 2;
            int nc = n >> 3, g8 = n & 7;
            int lane = g8*4 + c4;
            g_w1f[(size_t)(cls*9 + grp)*6144 + ((ks*8 + nc)*32 + lane)*2 + p]
                = __uint_as_float(tv);
        }
    } else {
        // conv2: 9 groups x 12288 entries, processed as 27 blocks x 4096
        for (int i = threadIdx.x; i < 4096; i += 256) {
            int gi = t * 4096 + i;
            int grp = gi / 12288;
            int r   = gi - grp * 12288;
            int n = r / 192, k = r - n * 192;
            int kw = k >> 6, cch = k & 63;
            int tap = grp * 3 + kw;
            float w = (n < 32) ? Wg[((size_t)(cls*32 + n)*64 + cch)*27 + tap]
                               : Wb[((size_t)(cls*32 + (n-32))*64 + cch)*27 + tap];
            u32 tv = tf32r(w);
            int ks = k >> 3, kc = k & 7, c4 = kc & 3, p = kc >> 2;
            int nc = n >> 3, g8 = n & 7;
            int lane = g8*4 + c4;
            g_w2f[(size_t)(cls*9 + grp)*12288 + ((ks*8 + nc)*32 + lane)*2 + p]
                = __uint_as_float(tv);
        }
    }
}

// ---------------------------------------------------------------------------
// conv1: tf32 32->64 + bias/relu, kw folded (9 groups, K=96).
// 512 thr (8m x 2n). A DOUBLE-buffered (2 x 620 x 144B), B dbuf 24KB.
// ---------------------------------------------------------------------------
#define ASTG1 (AROWS1 * ASTRIDE1)
#define BSTG1 24576
#define C1_DSMEM (2*ASTG1 + 2*BSTG1)
__global__ __launch_bounds__(512, 1)
void conv1_kernel(const int* __restrict__ ycls, const float* __restrict__ bsh) {
    extern __shared__ char dsm[];
    __shared__ float s_bias[64];

    int tile = blockIdx.x, pz = blockIdx.y + 1, b = blockIdx.z;
    int cls = ycls[b];
    int tid = threadIdx.x, wid = tid >> 5, lane = tid & 31;
    u32 base = (smem_u32(dsm) + 127) & ~127u;
    if (tid < 64) s_bias[tid] = bsh[cls*64 + tid];
    __syncthreads();

    int q0 = tile * MT1;
    size_t brow = (size_t)XOFF + (size_t)b*PDDD + (size_t)pz*PDD + q0;

    auto copyA = [&](int kd, int s) {
        u32 As = base + (u32)s * ASTG1;
        size_t blk = brow + (size_t)(kd - 1) * PDD - 51;
        for (int i = tid; i < AROWS1 * 8; i += 512) {
            int r = i >> 3, j = i & 7;
            cp16f(As + (u32)r*ASTRIDE1 + (u32)j*16,
                  (const char*)(g_xf + (blk + r) * 32) + j*16);
        }
    };
    auto copyB = [&](int g, int s) {
        u32 Bs = base + 2*ASTG1 + (u32)s * BSTG1;
        const char* bsrc = (const char*)(g_w1f + (size_t)(cls*9 + g) * 6144);
        for (int i = tid; i < 1536; i += 512) cp16f(Bs + i*16, bsrc + i*16);
    };

    float acc[4][4][4];
    #pragma unroll
    for (int i = 0; i < 4; i++)
        #pragma unroll
        for (int j = 0; j < 4; j++)
            #pragma unroll
            for (int q = 0; q < 4; q++) acc[i][j][q] = 0.f;

    int arow = (wid >> 1) * 64;
    int nslot = wid & 1;
    int lr4 = lane >> 2, lc4 = lane & 3;

    copyA(0, 0); copyB(0, 0); cp_commit();
    for (int g = 0; g < 9; g++) {
        int kd = g / 3, kh = g % 3;
        cp_wait0();
        __syncthreads();
        if (g + 1 < 9) copyB(g + 1, (g + 1) & 1);
        if (g == 2 || g == 5) copyA(kd + 1, (kd + 1) & 1);   // into dead buffer
        cp_commit();

        u32 AH = base + (u32)(kd & 1) * ASTG1;
        u32 Bs = base + 2*ASTG1 + (u32)(g & 1) * BSTG1;
        int rowoff = kh * 50;
        u32 abase[4];
        #pragma unroll
        for (int i = 0; i < 4; i++)
            abase[i] = AH + (u32)(arow + 16*i + lr4 + rowoff) * ASTRIDE1 + (u32)lc4 * 4;
        #pragma unroll
        for (int ks = 0; ks < 12; ks++) {
            u32 ro = (u32)(ks >> 2) * ASTRIDE1 + (u32)(ks & 3) * 32;
            u32 a[4][4];
            #pragma unroll
            for (int i = 0; i < 4; i++) {
                lds32(a[i][0], abase[i] + ro);
                lds32(a[i][1], abase[i] + 8*ASTRIDE1 + ro);
                lds32(a[i][2], abase[i] + ro + 16);
                lds32(a[i][3], abase[i] + 8*ASTRIDE1 + ro + 16);
            }
            u32 bf[4][2];
            #pragma unroll
            for (int nc = 0; nc < 4; nc++)
                lds64(bf[nc][0], bf[nc][1],
                      Bs + (u32)(((ks*8 + nslot*4 + nc)*32 + lane)*8));
            #pragma unroll
            for (int i = 0; i < 4; i++)
                #pragma unroll
                for (int nc = 0; nc < 4; nc++)
                    mmatf32(acc[i][nc], a[i], bf[nc][0], bf[nc][1]);
        }
    }

    // epilogue: bias + relu -> g_af (tf32-rounded fp32, channel-last)
    int qr = lane >> 2, qc = (lane & 3) * 2;
    #pragma unroll
    for (int i = 0; i < 4; i++) {
        #pragma unroll
        for (int rr = 0; rr < 2; rr++) {
            int m = arow + 16*i + 8*rr + qr;
            if (m >= MT1) continue;
            int q = q0 + m;
            int py = q / 50, px = q - py * 50;
            if (py < 1 || py > 48 || px < 1 || px > 48) continue;
            size_t lin = (size_t)XOFF + (size_t)b*PDDD + (size_t)pz*PDD + q;
            #pragma unroll
            for (int nc = 0; nc < 4; nc++) {
                int ch = nslot*32 + nc*8 + qc;
                float v0 = fmaxf(acc[i][nc][rr*2 + 0] + s_bias[ch],     0.f);
                float v1 = fmaxf(acc[i][nc][rr*2 + 1] + s_bias[ch + 1], 0.f);
                float2 st = make_float2(__uint_as_float(tf32r(v0)),
                                        __uint_as_float(tf32r(v1)));
                *(float2*)(g_af + lin*64 + ch) = st;
            }
        }
    }
}

// ---------------------------------------------------------------------------
// conv2: tf32 64->64 (gamma|beta) + InstanceNorm, kw folded (9 groups, K=192).
// MT=250, 512 thr (8m x 2n). A single (360 x 272B), B dbuf 48KB.
// ---------------------------------------------------------------------------
#define ASTG2 (AROWS2 * ASTRIDE2)
#define BSTG2 49152
#define C2_DSMEM (ASTG2 + 2*BSTG2)
__global__ __launch_bounds__(512, 1)
void conv2_kernel(const float* __restrict__ x,
                  const float* __restrict__ bg, const float* __restrict__ bb_,
                  const int* __restrict__ ycls, float* __restrict__ out) {
    extern __shared__ char dsm[];
    __shared__ float s_mu[32], s_rs[32], s_bg[32], s_bb[32];

    int tile = blockIdx.x, pz = blockIdx.y + 1, b = blockIdx.z;
    int cls = ycls[b];
    int tid = threadIdx.x, wid = tid >> 5, lane = tid & 31;
    u32 base = (smem_u32(dsm) + 127) & ~127u;
    if (tid < 32) {
        s_mu[tid] = g_mu[b*32 + tid];
        s_rs[tid] = g_rsig[b*32 + tid];
        s_bg[tid] = bg[cls*32 + tid];
        s_bb[tid] = bb_[cls*32 + tid];
    }
    __syncthreads();

    int q0 = tile * MT2;
    size_t brow = (size_t)XOFF + (size_t)b*PDDD + (size_t)pz*PDD + q0;
    u32 AH = base;

    auto copyA = [&](int kd) {
        size_t blk = brow + (size_t)(kd - 1) * PDD - 51;
        for (int i = tid; i < AROWS2 * 16; i += 512) {
            int r = i >> 4, j = i & 15;
            cp16f(AH + (u32)r*ASTRIDE2 + (u32)j*16,
                  (const char*)(g_af + (blk + r) * 64) + j*16);
        }
    };
    auto copyB = [&](int g, int s) {
        u32 Bs = base + ASTG2 + (u32)s * BSTG2;
        const char* bsrc = (const char*)(g_w2f + (size_t)(cls*9 + g) * 12288);
        for (int i = tid; i < 3072; i += 512) cp16f(Bs + i*16, bsrc + i*16);
    };

    float acc[2][4][4];
    #pragma unroll
    for (int i = 0; i < 2; i++)
        #pragma unroll
        for (int j = 0; j < 4; j++)
            #pragma unroll
            for (int q = 0; q < 4; q++) acc[i][j][q] = 0.f;

    int arow = (wid >> 1) * 32;
    int nslot = wid & 1;
    int lr4 = lane >> 2, lc4 = lane & 3;

    copyA(0); copyB(0, 0); cp_commit();
    for (int g = 0; g < 9; g++) {
        int kd = g / 3, kh = g % 3;
        if (g == 3 || g == 6) {
            __syncthreads();           // all warps done reading old A
            copyA(kd); cp_commit();
        }
        cp_wait0();
        __syncthreads();
        if (g + 1 < 9) { copyB(g + 1, (g + 1) & 1); cp_commit(); }

        u32 Bs = base + ASTG2 + (u32)(g & 1) * BSTG2;
        int rowoff = kh * 50;
        u32 abase[2];
        #pragma unroll
        for (int i = 0; i < 2; i++)
            abase[i] = AH + (u32)(arow + 16*i + lr4 + rowoff) * ASTRIDE2 + (u32)lc4 * 4;
        #pragma unroll
        for (int ks = 0; ks < 24; ks++) {
            u32 ro = (u32)(ks >> 3) * ASTRIDE2 + (u32)(ks & 7) * 32;
            u32 a[2][4];
            #pragma unroll
            for (int i = 0; i < 2; i++) {
                lds32(a[i][0], abase[i] + ro);
                lds32(a[i][1], abase[i] + 8*ASTRIDE2 + ro);
                lds32(a[i][2], abase[i] + ro + 16);
                lds32(a[i][3], abase[i] + 8*ASTRIDE2 + ro + 16);
            }
            u32 bf[4][2];
            #pragma unroll
            for (int nc = 0; nc < 4; nc++)
                lds64(bf[nc][0], bf[nc][1],
                      Bs + (u32)(((ks*8 + nslot*4 + nc)*32 + lane)*8));
            #pragma unroll
            for (int i = 0; i < 2; i++)
                #pragma unroll
                for (int nc = 0; nc < 4; nc++)
                    mmatf32(acc[i][nc], a[i], bf[nc][0], bf[nc][1]);
        }
    }

    // ---------- exchange epilogue ----------
    __syncthreads();
    float* sg = (float*)(dsm + (base - smem_u32(dsm)));
    float* sb = sg + 256 * 33;

    int qr = lane >> 2, qc = (lane & 3) * 2;
    #pragma unroll
    for (int i = 0; i < 2; i++) {
        #pragma unroll
        for (int rr = 0; rr < 2; rr++) {
            int m = arow + 16*i + 8*rr + qr;
            #pragma unroll
            for (int nc = 0; nc < 4; nc++) {
                int n = nslot*32 + nc*8 + qc;
                float v0 = acc[i][nc][rr*2 + 0];
                float v1 = acc[i][nc][rr*2 + 1];
                if (n < 32) { sg[m*33 + n] = v0; sg[m*33 + n + 1] = v1; }
                else        { sb[m*33 + n - 32] = v0; sb[m*33 + n - 31] = v1; }
            }
        }
    }
    __syncthreads();

    if (tid < 2 * MT2) {
        int m = tid >> 1, half = tid & 1;
        int q = q0 + m;
        int py = q / 50, px = q - py * 50;
        if (py >= 1 && py <= 48 && px >= 1 && px <= 48) {
            size_t sidx = (size_t)b*32*VNNN + (size_t)(pz-1)*VNN + (py-1)*VN + (px-1);
            #pragma unroll
            for (int c = 0; c < 16; c++) {
                int ch = half*16 + c;
                float gm = sg[m*33 + ch] + s_bg[ch];
                float bt = sb[m*33 + ch] + s_bb[ch];
                float xv = x[sidx + (size_t)ch * VNNN];
                out[sidx + (size_t)ch * VNNN] =
                    (xv - s_mu[ch]) * s_rs[ch] * (1.f + gm) + bt;
            }
        }
    }
}

// ---------------------------------------------------------------------------
extern "C" void kernel_launch(void* const* d_in, const int* in_sizes, int n_in,
                              void* d_out, int out_size) {
    const float* x       = (const float*)d_in[0];
    const int*   y       = (const int*)d_in[1];
    const float* Wshared = (const float*)d_in[2];
    const float* bshared = (const float*)d_in[3];
    const float* Wgamma  = (const float*)d_in[4];
    const float* bgamma  = (const float*)d_in[5];
    const float* Wbeta   = (const float*)d_in[6];
    const float* bbeta   = (const float*)d_in[7];
    float* out = (float*)d_out;

    cudaFuncSetAttribute(conv1_kernel, cudaFuncAttributeMaxDynamicSharedMemorySize, C1_DSMEM);
    cudaFuncSetAttribute(conv2_kernel, cudaFuncAttributeMaxDynamicSharedMemorySize, C2_DSMEM);

    stats_kernel<<<NB * 32, 256>>>(x);
    xpose_kernel<<<dim3(PD, NB), 256>>>(x);
    prepb_kernel<<<dim3(27, 8), 256>>>(Wshared, Wgamma, Wbeta);

    conv1_kernel<<<dim3(NTILE1, 48, NB), 512, C1_DSMEM>>>(y, bshared);
    conv2_kernel<<<dim3(NTILE2, 48, NB), 512, C2_DSMEM>>>(x, bgamma, bbeta, y, out);
}

// round 15
// speedup vs baseline: 1.0241x; 1.0241x over previous
#include <cuda_runtime.h>
#include <cuda_bf16.h>
#include <cstdint>

typedef unsigned int u32;
typedef unsigned long long u64;

#define VN 48
#define VNN 2304
#define VNNN 110592
#define NB 8
#define SP_EPS 1e-5f
#define PD 50
#define PDD 2500
#define PDDD 125000
#define XOFF 128

// conv1 (occ 2)
#define NTILE1 10
#define MT1 250
#define AROWS1 360
#define ASTRIDE1 144
// conv2 (R12 shape)
#define NTILE2 5
#define MT2 500
#define AROWS2 620
#define ASTRIDE2 272

// ---------------- device scratch ----------------
__device__ float g_xf [((size_t)NB * PDDD + 2 * XOFF) * 32];
__device__ float g_af [((size_t)NB * PDDD + 2 * XOFF) * 64];
__device__ float g_w1f[4 * 9 * 6144];      // conv1: per (cls, kd*3+kh): 64n x 96k
__device__ float g_w2f[4 * 27 * 4096];     // conv2: per (cls, tap): 64n x 64k
__device__ float g_mu[NB * 32];
__device__ float g_rsig[NB * 32];

// ---------------- helpers ----------------
__device__ __forceinline__ u32 smem_u32(const void* p) {
    u32 a; asm("{ .reg .u64 t; cvta.to.shared.u64 t, %1; cvt.u32.u64 %0, t; }"
               : "=r"(a) : "l"(p));
    return a;
}
__device__ __forceinline__ void cp16f(u32 dst, const void* src) {
    asm volatile("cp.async.ca.shared.global [%0], [%1], 16;" :: "r"(dst), "l"(src));
}
__device__ __forceinline__ void cp_commit() { asm volatile("cp.async.commit_group;"); }
__device__ __forceinline__ void cp_wait0()  { asm volatile("cp.async.wait_group 0;" ::: "memory"); }
__device__ __forceinline__ u32 tf32r(float v) {
    u32 r; asm("cvt.rna.tf32.f32 %0, %1;" : "=r"(r) : "f"(v)); return r;
}
__device__ __forceinline__ void lds32(u32& r, u32 addr) {
    asm volatile("ld.shared.b32 %0, [%1];" : "=r"(r) : "r"(addr));
}
__device__ __forceinline__ void lds64(u32& r0, u32& r1, u32 addr) {
    asm volatile("ld.shared.v2.b32 {%0,%1}, [%2];" : "=r"(r0), "=r"(r1) : "r"(addr));
}
__device__ __forceinline__ void mmatf32(float* d, const u32* a, u32 b0, u32 b1) {
    asm volatile("mma.sync.aligned.m16n8k8.row.col.f32.tf32.tf32.f32 "
        "{%0,%1,%2,%3}, {%4,%5,%6,%7}, {%8,%9}, {%0,%1,%2,%3};"
        : "+f"(d[0]), "+f"(d[1]), "+f"(d[2]), "+f"(d[3])
        : "r"(a[0]), "r"(a[1]), "r"(a[2]), "r"(a[3]), "r"(b0), "r"(b1));
}

// ---------------------------------------------------------------------------
// stats
// ---------------------------------------------------------------------------
__global__ void stats_kernel(const float* __restrict__ x) {
    int bc = blockIdx.x;
    const float4* xp = reinterpret_cast<const float4*>(x + (size_t)bc * VNNN);
    float s = 0.f, ss = 0.f;
    for (int i = threadIdx.x; i < VNNN / 4; i += blockDim.x) {
        float4 v = xp[i];
        s  += v.x + v.y + v.z + v.w;
        ss += v.x*v.x + v.y*v.y + v.z*v.z + v.w*v.w;
    }
    __shared__ float sh_s[8], sh_ss[8];
    #pragma unroll
    for (int o = 16; o; o >>= 1) {
        s  += __shfl_down_sync(0xffffffffu, s, o);
        ss += __shfl_down_sync(0xffffffffu, ss, o);
    }
    int w = threadIdx.x >> 5, l = threadIdx.x & 31;
    if (l == 0) { sh_s[w] = s; sh_ss[w] = ss; }
    __syncthreads();
    if (w == 0) {
        s  = (l < 8) ? sh_s[l]  : 0.f;
        ss = (l < 8) ? sh_ss[l] : 0.f;
        #pragma unroll
        for (int o = 4; o; o >>= 1) {
            s  += __shfl_down_sync(0xffffffffu, s, o);
            ss += __shfl_down_sync(0xffffffffu, ss, o);
        }
        if (l == 0) {
            float mu  = s / (float)VNNN;
            float var = ss / (float)VNNN - mu * mu;
            g_mu[bc] = mu; g_rsig[bc] = rsqrtf(var + SP_EPS);
        }
    }
}

// ---------------------------------------------------------------------------
// xpose + zero g_af halo (merged)
// ---------------------------------------------------------------------------
__global__ __launch_bounds__(256)
void xpose_kernel(const float* __restrict__ x) {
    int pz = blockIdx.x, b = blockIdx.y;
    for (int c = threadIdx.x; c < PDD; c += 256) {
        int py = c / PD, px = c - py * PD;
        size_t lin = (size_t)XOFF + (size_t)b*PDDD + (size_t)pz*PDD + py*PD + px;
        float4* d = (float4*)(g_xf + lin * 32);
        bool inside = (pz >= 1 && pz <= 48 && py >= 1 && py <= 48 && px >= 1 && px <= 48);
        if (inside) {
            const float* xb = x + (size_t)b*32*VNNN + (size_t)(pz-1)*VNN + (py-1)*VN + (px-1);
            u32 p[32];
            #pragma unroll
            for (int q = 0; q < 32; q++) p[q] = tf32r(xb[(size_t)q * VNNN]);
            #pragma unroll
            for (int i = 0; i < 8; i++) d[i] = ((float4*)p)[i];
        } else {
            float4 z = make_float4(0.f,0.f,0.f,0.f);
            #pragma unroll
            for (int i = 0; i < 8; i++) d[i] = z;
            float4* da = (float4*)(g_af + lin * 64);
            #pragma unroll
            for (int i = 0; i < 16; i++) da[i] = z;
        }
    }
}

// ---------------------------------------------------------------------------
// Pre-arranged tf32 B tiles, lane-major pair layout
// conv1: folded-kw groups (kd,kh): 64n x 96k; conv2: per-tap 64n x 64k
// ---------------------------------------------------------------------------
__global__ void prepb_kernel(const float* __restrict__ Ws,
                             const float* __restrict__ Wg,
                             const float* __restrict__ Wb) {
    int t = blockIdx.x;                 // 0..26
    int cls = blockIdx.y & 3;
    int which = blockIdx.y >> 2;
    if (which == 0) {
        for (int i = threadIdx.x; i < 2048; i += 256) {
            int gi = t * 2048 + i;
            int grp = gi / 6144;
            int r   = gi - grp * 6144;
            int n = r / 96, k = r - n * 96;
            int kw = k >> 5, cch = k & 31;
            int tap = grp * 3 + kw;
            float w = Ws[((size_t)(cls*64 + n)*32 + cch)*27 + tap];
            u32 tv = tf32r(w);
            int ks = k >> 3, kc = k & 7, c4 = kc & 3, p = kc >> 2;
            int nc = n >> 3, g8 = n & 7;
            int lane = g8*4 + c4;
            g_w1f[(size_t)(cls*9 + grp)*6144 + ((ks*8 + nc)*32 + lane)*2 + p]
                = __uint_as_float(tv);
        }
    } else {
        float* o = g_w2f + (size_t)(cls*27 + t) * 4096;
        for (int i = threadIdx.x; i < 4096; i += 256) {
            int n = i >> 6, k = i & 63;
            float w = (n < 32) ? Wg[((size_t)(cls*32 + n)*64 + k)*27 + t]
                               : Wb[((size_t)(cls*32 + (n-32))*64 + k)*27 + t];
            u32 tv = tf32r(w);
            int ks = k >> 3, kc = k & 7, c4 = kc & 3, p = kc >> 2;
            int nc = n >> 3, g8 = n & 7;
            int lane = g8*4 + c4;
            o[((ks*8 + nc)*32 + lane)*2 + p] = __uint_as_float(tv);
        }
    }
}

// ---------------------------------------------------------------------------
// conv1: tf32 32->64 + bias/relu, kw folded (9 groups, K=96).
// 256 thr (4m x 2n), MT=250, occ 2. A single (360 x 144B), B dbuf 24KB.
// ---------------------------------------------------------------------------
#define ASTG1 (AROWS1 * ASTRIDE1)
#define BSTG1 24576
#define C1_DSMEM (ASTG1 + 2*BSTG1)
__global__ __launch_bounds__(256, 2)
void conv1_kernel(const int* __restrict__ ycls, const float* __restrict__ bsh) {
    extern __shared__ char dsm[];
    __shared__ float s_bias[64];

    int tile = blockIdx.x, pz = blockIdx.y + 1, b = blockIdx.z;
    int cls = ycls[b];
    int tid = threadIdx.x, wid = tid >> 5, lane = tid & 31;
    u32 base = (smem_u32(dsm) + 127) & ~127u;
    if (tid < 64) s_bias[tid] = bsh[cls*64 + tid];
    __syncthreads();

    int q0 = tile * MT1;
    size_t brow = (size_t)XOFF + (size_t)b*PDDD + (size_t)pz*PDD + q0;
    u32 AH = base;

    auto copyA = [&](int kd) {
        size_t blk = brow + (size_t)(kd - 1) * PDD - 51;
        for (int i = tid; i < AROWS1 * 8; i += 256) {
            int r = i >> 3, j = i & 7;
            cp16f(AH + (u32)r*ASTRIDE1 + (u32)j*16,
                  (const char*)(g_xf + (blk + r) * 32) + j*16);
        }
    };
    auto copyB = [&](int g, int s) {
        u32 Bs = base + ASTG1 + (u32)s * BSTG1;
        const char* bsrc = (const char*)(g_w1f + (size_t)(cls*9 + g) * 6144);
        for (int i = tid; i < 1536; i += 256) cp16f(Bs + i*16, bsrc + i*16);
    };

    float acc[4][4][4];
    #pragma unroll
    for (int i = 0; i < 4; i++)
        #pragma unroll
        for (int j = 0; j < 4; j++)
            #pragma unroll
            for (int q = 0; q < 4; q++) acc[i][j][q] = 0.f;

    int arow = (wid >> 1) * 64;
    int nslot = wid & 1;
    int lr4 = lane >> 2, lc4 = lane & 3;

    copyA(0); copyB(0, 0); cp_commit();
    for (int g = 0; g < 9; g++) {
        int kd = g / 3, kh = g % 3;
        if (g == 3 || g == 6) {
            __syncthreads();           // all warps done reading old A
            copyA(kd); cp_commit();
        }
        cp_wait0();
        __syncthreads();
        if (g + 1 < 9) { copyB(g + 1, (g + 1) & 1); cp_commit(); }

        u32 Bs = base + ASTG1 + (u32)(g & 1) * BSTG1;
        int rowoff = kh * 50;
        u32 abase[4];
        #pragma unroll
        for (int i = 0; i < 4; i++)
            abase[i] = AH + (u32)(arow + 16*i + lr4 + rowoff) * ASTRIDE1 + (u32)lc4 * 4;
        #pragma unroll
        for (int ks = 0; ks < 12; ks++) {
            u32 ro = (u32)(ks >> 2) * ASTRIDE1 + (u32)(ks & 3) * 32;
            u32 a[4][4];
            #pragma unroll
            for (int i = 0; i < 4; i++) {
                lds32(a[i][0], abase[i] + ro);
                lds32(a[i][1], abase[i] + 8*ASTRIDE1 + ro);
                lds32(a[i][2], abase[i] + ro + 16);
                lds32(a[i][3], abase[i] + 8*ASTRIDE1 + ro + 16);
            }
            u32 bf[4][2];
            #pragma unroll
            for (int nc = 0; nc < 4; nc++)
                lds64(bf[nc][0], bf[nc][1],
                      Bs + (u32)(((ks*8 + nslot*4 + nc)*32 + lane)*8));
            #pragma unroll
            for (int i = 0; i < 4; i++)
                #pragma unroll
                for (int nc = 0; nc < 4; nc++)
                    mmatf32(acc[i][nc], a[i], bf[nc][0], bf[nc][1]);
        }
    }

    // epilogue: bias + relu -> g_af (tf32-rounded fp32, channel-last)
    int qr = lane >> 2, qc = (lane & 3) * 2;
    #pragma unroll
    for (int i = 0; i < 4; i++) {
        #pragma unroll
        for (int rr = 0; rr < 2; rr++) {
            int m = arow + 16*i + 8*rr + qr;
            if (m >= MT1) continue;
            int q = q0 + m;
            int py = q / 50, px = q - py * 50;
            if (py < 1 || py > 48 || px < 1 || px > 48) continue;
            size_t lin = (size_t)XOFF + (size_t)b*PDDD + (size_t)pz*PDD + q;
            #pragma unroll
            for (int nc = 0; nc < 4; nc++) {
                int ch = nslot*32 + nc*8 + qc;
                float v0 = fmaxf(acc[i][nc][rr*2 + 0] + s_bias[ch],     0.f);
                float v1 = fmaxf(acc[i][nc][rr*2 + 1] + s_bias[ch + 1], 0.f);
                float2 st = make_float2(__uint_as_float(tf32r(v0)),
                                        __uint_as_float(tf32r(v1)));
                *(float2*)(g_af + lin*64 + ch) = st;
            }
        }
    }
}

// ---------------------------------------------------------------------------
// conv2: tf32 64->64 (gamma|beta) + InstanceNorm (exact R12 structure).
// 512 thr (8m x 2n), occ 1. A single (620 x 272B), B dbuf 16KB.
// ---------------------------------------------------------------------------
#define ASTG2 (AROWS2 * ASTRIDE2)
#define C2_DSMEM (ASTG2 + 2*16384)
__global__ __launch_bounds__(512, 1)
void conv2_kernel(const float* __restrict__ x,
                  const float* __restrict__ bg, const float* __restrict__ bb_,
                  const int* __restrict__ ycls, float* __restrict__ out) {
    extern __shared__ char dsm[];
    __shared__ float s_mu[32], s_rs[32], s_bg[32], s_bb[32];

    int tile = blockIdx.x, pz = blockIdx.y + 1, b = blockIdx.z;
    int cls = ycls[b];
    int tid = threadIdx.x, wid = tid >> 5, lane = tid & 31;
    u32 base = (smem_u32(dsm) + 127) & ~127u;
    if (tid < 32) {
        s_mu[tid] = g_mu[b*32 + tid];
        s_rs[tid] = g_rsig[b*32 + tid];
        s_bg[tid] = bg[cls*32 + tid];
        s_bb[tid] = bb_[cls*32 + tid];
    }
    __syncthreads();

    int q0 = tile * MT2;
    size_t brow = (size_t)XOFF + (size_t)b*PDDD + (size_t)pz*PDD + q0;
    u32 AH = base;

    auto copyA = [&](int kd) {
        size_t blk = brow + (size_t)(kd - 1) * PDD - 51;
        for (int i = tid; i < AROWS2 * 16; i += 512) {
            int r = i >> 4, j = i & 15;
            cp16f(AH + (u32)r*ASTRIDE2 + (u32)j*16,
                  (const char*)(g_af + (blk + r) * 64) + j*16);
        }
    };
    auto copyB = [&](int t, int s) {
        u32 Bs = base + ASTG2 + (u32)s * 16384;
        const char* bsrc = (const char*)(g_w2f + (size_t)(cls*27 + t) * 4096);
        for (int i = tid; i < 1024; i += 512) cp16f(Bs + i*16, bsrc + i*16);
    };

    float acc[4][4][4];
    #pragma unroll
    for (int i = 0; i < 4; i++)
        #pragma unroll
        for (int j = 0; j < 4; j++)
            #pragma unroll
            for (int q = 0; q < 4; q++) acc[i][j][q] = 0.f;

    int arow = (wid >> 1) * 64;
    int nslot = wid & 1;
    int lr4 = lane >> 2, lc4 = lane & 3;

    copyA(0); copyB(0, 0); cp_commit();
    for (int t = 0; t < 27; t++) {
        int kd = t / 9, kh = (t % 9) / 3, kw = t % 3;
        cp_wait0();
        __syncthreads();
        int nt = t + 1;
        if (nt < 27 && nt % 9 != 0) { copyB(nt, nt & 1); cp_commit(); }
        u32 Bs = base + ASTG2 + (u32)(t & 1) * 16384;
        int rowoff = kh * 50 + kw;
        u32 abase[4];
        #pragma unroll
        for (int i = 0; i < 4; i++)
            abase[i] = AH + (u32)(arow + 16*i + lr4 + rowoff) * ASTRIDE2 + (u32)lc4 * 4;
        #pragma unroll
        for (int ks = 0; ks < 8; ks++) {
            u32 a[4][4];
            #pragma unroll
            for (int i = 0; i < 4; i++) {
                lds32(a[i][0], abase[i] + ks*32);
                lds32(a[i][1], abase[i] + 8*ASTRIDE2 + ks*32);
                lds32(a[i][2], abase[i] + ks*32 + 16);
                lds32(a[i][3], abase[i] + 8*ASTRIDE2 + ks*32 + 16);
            }
            u32 bf[4][2];
            #pragma unroll
            for (int nc = 0; nc < 4; nc++)
                lds64(bf[nc][0], bf[nc][1],
                      Bs + (u32)(((ks*8 + nslot*4 + nc)*32 + lane)*8));
            #pragma unroll
            for (int i = 0; i < 4; i++)
                #pragma unroll
                for (int nc = 0; nc < 4; nc++)
                    mmatf32(acc[i][nc], a[i], bf[nc][0], bf[nc][1]);
        }
        if (nt < 27 && nt % 9 == 0) {
            __syncthreads();
            copyA(nt / 9); copyB(nt, nt & 1); cp_commit();
        }
    }

    // ---------- exchange epilogue ----------
    __syncthreads();
    float* sg = (float*)(dsm + (base - smem_u32(dsm)));
    float* sb = sg + 512 * 33;

    int qr = lane >> 2, qc = (lane & 3) * 2;
    #pragma unroll
    for (int i = 0; i < 4; i++) {
        #pragma unroll
        for (int rr = 0; rr < 2; rr++) {
            int m = arow + 16*i + 8*rr + qr;
            #pragma unroll
            for (int nc = 0; nc < 4; nc++) {
                int n = nslot*32 + nc*8 + qc;
                float v0 = acc[i][nc][rr*2 + 0];
                float v1 = acc[i][nc][rr*2 + 1];
                if (n < 32) { sg[m*33 + n] = v0; sg[m*33 + n + 1] = v1; }
                else        { sb[m*33 + n - 32] = v0; sb[m*33 + n - 31] = v1; }
            }
        }
    }
    __syncthreads();

    if (tid < MT2) {
        int q = q0 + tid;
        int py = q / 50, px = q - py * 50;
        if (py >= 1 && py <= 48 && px >= 1 && px <= 48) {
            size_t sidx = (size_t)b*32*VNNN + (size_t)(pz-1)*VNN + (py-1)*VN + (px-1);
            #pragma unroll 8
            for (int ch = 0; ch < 32; ch++) {
                float gm = sg[tid*33 + ch] + s_bg[ch];
                float bt = sb[tid*33 + ch] + s_bb[ch];
                float xv = x[sidx + (size_t)ch * VNNN];
                out[sidx + (size_t)ch * VNNN] =
                    (xv - s_mu[ch]) * s_rs[ch] * (1.f + gm) + bt;
            }
        }
    }
}

// ---------------------------------------------------------------------------
extern "C" void kernel_launch(void* const* d_in, const int* in_sizes, int n_in,
                              void* d_out, int out_size) {
    const float* x       = (const float*)d_in[0];
    const int*   y       = (const int*)d_in[1];
    const float* Wshared = (const float*)d_in[2];
    const float* bshared = (const float*)d_in[3];
    const float* Wgamma  = (const float*)d_in[4];
    const float* bgamma  = (const float*)d_in[5];
    const float* Wbeta   = (const float*)d_in[6];
    const float* bbeta   = (const float*)d_in[7];
    float* out = (float*)d_out;

    cudaFuncSetAttribute(conv1_kernel, cudaFuncAttributeMaxDynamicSharedMemorySize, C1_DSMEM);
    cudaFuncSetAttribute(conv2_kernel, cudaFuncAttributeMaxDynamicSharedMemorySize, C2_DSMEM);

    stats_kernel<<<NB * 32, 256>>>(x);
    xpose_kernel<<<dim3(PD, NB), 256>>>(x);
    prepb_kernel<<<dim3(27, 8), 256>>>(Wshared, Wgamma, Wbeta);

    conv1_kernel<<<dim3(NTILE1, 48, NB), 256, C1_DSMEM>>>(y, bshared);
    conv2_kernel<<<dim3(NTILE2, 48, NB), 512, C2_DSMEM>>>(x, bgamma, bbeta, y, out);
}

// round 16
// speedup vs baseline: 1.0490x; 1.0243x over previous
#include <cuda_runtime.h>
#include <cuda_bf16.h>
#include <cstdint>

typedef unsigned int u32;
typedef unsigned long long u64;

#define VN 48
#define VNN 2304
#define VNNN 110592
#define NB 8
#define SP_EPS 1e-5f
#define PD 50
#define PDD 2500
#define PDDD 125000
#define XOFF 128

#define NTILE 5
#define MT 500
#define AROWS 620
#define ASTRIDE1 144
#define ASTRIDE2 272

// ---------------- device scratch ----------------
__device__ float g_xf [((size_t)NB * PDDD + 2 * XOFF) * 32];
__device__ float g_af [((size_t)NB * PDDD + 2 * XOFF) * 64];
__device__ float g_w1f[4 * 9 * 6144];      // conv1: per (cls, kd*3+kh): 64n x 96k
__device__ float g_w2f[4 * 27 * 4096];     // conv2: per (cls, tap): 64n x 64k
__device__ float g_mu[NB * 32];
__device__ float g_rsig[NB * 32];

// ---------------- helpers ----------------
__device__ __forceinline__ u32 smem_u32(const void* p) {
    u32 a; asm("{ .reg .u64 t; cvta.to.shared.u64 t, %1; cvt.u32.u64 %0, t; }"
               : "=r"(a) : "l"(p));
    return a;
}
__device__ __forceinline__ void cp16f(u32 dst, const void* src) {
    asm volatile("cp.async.ca.shared.global [%0], [%1], 16;" :: "r"(dst), "l"(src));
}
__device__ __forceinline__ void cp_commit() { asm volatile("cp.async.commit_group;"); }
__device__ __forceinline__ void cp_wait0()  { asm volatile("cp.async.wait_group 0;" ::: "memory"); }
__device__ __forceinline__ u32 tf32r(float v) {
    u32 r; asm("cvt.rna.tf32.f32 %0, %1;" : "=r"(r) : "f"(v)); return r;
}
__device__ __forceinline__ void lds32(u32& r, u32 addr) {
    asm volatile("ld.shared.b32 %0, [%1];" : "=r"(r) : "r"(addr));
}
__device__ __forceinline__ void lds64(u32& r0, u32& r1, u32 addr) {
    asm volatile("ld.shared.v2.b32 {%0,%1}, [%2];" : "=r"(r0), "=r"(r1) : "r"(addr));
}
__device__ __forceinline__ void mmatf32(float* d, const u32* a, u32 b0, u32 b1) {
    asm volatile("mma.sync.aligned.m16n8k8.row.col.f32.tf32.tf32.f32 "
        "{%0,%1,%2,%3}, {%4,%5,%6,%7}, {%8,%9}, {%0,%1,%2,%3};"
        : "+f"(d[0]), "+f"(d[1]), "+f"(d[2]), "+f"(d[3])
        : "r"(a[0]), "r"(a[1]), "r"(a[2]), "r"(a[3]), "r"(b0), "r"(b1));
}

// ---------------------------------------------------------------------------
// stats
// ---------------------------------------------------------------------------
__global__ void stats_kernel(const float* __restrict__ x) {
    int bc = blockIdx.x;
    const float4* xp = reinterpret_cast<const float4*>(x + (size_t)bc * VNNN);
    float s = 0.f, ss = 0.f;
    for (int i = threadIdx.x; i < VNNN / 4; i += blockDim.x) {
        float4 v = xp[i];
        s  += v.x + v.y + v.z + v.w;
        ss += v.x*v.x + v.y*v.y + v.z*v.z + v.w*v.w;
    }
    __shared__ float sh_s[8], sh_ss[8];
    #pragma unroll
    for (int o = 16; o; o >>= 1) {
        s  += __shfl_down_sync(0xffffffffu, s, o);
        ss += __shfl_down_sync(0xffffffffu, ss, o);
    }
    int w = threadIdx.x >> 5, l = threadIdx.x & 31;
    if (l == 0) { sh_s[w] = s; sh_ss[w] = ss; }
    __syncthreads();
    if (w == 0) {
        s  = (l < 8) ? sh_s[l]  : 0.f;
        ss = (l < 8) ? sh_ss[l] : 0.f;
        #pragma unroll
        for (int o = 4; o; o >>= 1) {
            s  += __shfl_down_sync(0xffffffffu, s, o);
            ss += __shfl_down_sync(0xffffffffu, ss, o);
        }
        if (l == 0) {
            float mu  = s / (float)VNNN;
            float var = ss / (float)VNNN - mu * mu;
            g_mu[bc] = mu; g_rsig[bc] = rsqrtf(var + SP_EPS);
        }
    }
}

// ---------------------------------------------------------------------------
// xpose + zero g_af halo (merged)
// ---------------------------------------------------------------------------
__global__ __launch_bounds__(256)
void xpose_kernel(const float* __restrict__ x) {
    int pz = blockIdx.x, b = blockIdx.y;
    for (int c = threadIdx.x; c < PDD; c += 256) {
        int py = c / PD, px = c - py * PD;
        size_t lin = (size_t)XOFF + (size_t)b*PDDD + (size_t)pz*PDD + py*PD + px;
        float4* d = (float4*)(g_xf + lin * 32);
        bool inside = (pz >= 1 && pz <= 48 && py >= 1 && py <= 48 && px >= 1 && px <= 48);
        if (inside) {
            const float* xb = x + (size_t)b*32*VNNN + (size_t)(pz-1)*VNN + (py-1)*VN + (px-1);
            u32 p[32];
            #pragma unroll
            for (int q = 0; q < 32; q++) p[q] = tf32r(xb[(size_t)q * VNNN]);
            #pragma unroll
            for (int i = 0; i < 8; i++) d[i] = ((float4*)p)[i];
        } else {
            float4 z = make_float4(0.f,0.f,0.f,0.f);
            #pragma unroll
            for (int i = 0; i < 8; i++) d[i] = z;
            float4* da = (float4*)(g_af + lin * 64);
            #pragma unroll
            for (int i = 0; i < 16; i++) da[i] = z;
        }
    }
}

// ---------------------------------------------------------------------------
// Pre-arranged tf32 B tiles, lane-major pair layout
// ---------------------------------------------------------------------------
__global__ void prepb_kernel(const float* __restrict__ Ws,
                             const float* __restrict__ Wg,
                             const float* __restrict__ Wb) {
    int t = blockIdx.x;
    int cls = blockIdx.y & 3;
    int which = blockIdx.y >> 2;
    if (which == 0) {
        for (int i = threadIdx.x; i < 2048; i += 256) {
            int gi = t * 2048 + i;
            int grp = gi / 6144;
            int r   = gi - grp * 6144;
            int n = r / 96, k = r - n * 96;
            int kw = k >> 5, cch = k & 31;
            int tap = grp * 3 + kw;
            float w = Ws[((size_t)(cls*64 + n)*32 + cch)*27 + tap];
            u32 tv = tf32r(w);
            int ks = k >> 3, kc = k & 7, c4 = kc & 3, p = kc >> 2;
            int nc = n >> 3, g8 = n & 7;
            int lane = g8*4 + c4;
            g_w1f[(size_t)(cls*9 + grp)*6144 + ((ks*8 + nc)*32 + lane)*2 + p]
                = __uint_as_float(tv);
        }
    } else {
        float* o = g_w2f + (size_t)(cls*27 + t) * 4096;
        for (int i = threadIdx.x; i < 4096; i += 256) {
            int n = i >> 6, k = i & 63;
            float w = (n < 32) ? Wg[((size_t)(cls*32 + n)*64 + k)*27 + t]
                               : Wb[((size_t)(cls*32 + (n-32))*64 + k)*27 + t];
            u32 tv = tf32r(w);
            int ks = k >> 3, kc = k & 7, c4 = kc & 3, p = kc >> 2;
            int nc = n >> 3, g8 = n & 7;
            int lane = g8*4 + c4;
            o[((ks*8 + nc)*32 + lane)*2 + p] = __uint_as_float(tv);
        }
    }
}

// ---------------------------------------------------------------------------
// conv1: tf32 32->64 + bias/relu, kw folded (9 groups, K=96).
// 256 thr, 8 warps each m64 x n64. A single (620 x 144B), B dbuf 24KB.
// ---------------------------------------------------------------------------
#define ASTG1 (AROWS * ASTRIDE1)
#define BSTG1 24576
#define C1_DSMEM (ASTG1 + 2*BSTG1)
__global__ __launch_bounds__(256, 1)
void conv1_kernel(const int* __restrict__ ycls, const float* __restrict__ bsh) {
    extern __shared__ char dsm[];
    __shared__ float s_bias[64];

    int tile = blockIdx.x, pz = blockIdx.y + 1, b = blockIdx.z;
    int cls = ycls[b];
    int tid = threadIdx.x, wid = tid >> 5, lane = tid & 31;
    u32 base = (smem_u32(dsm) + 127) & ~127u;
    if (tid < 64) s_bias[tid] = bsh[cls*64 + tid];
    __syncthreads();

    int q0 = tile * MT;
    size_t brow = (size_t)XOFF + (size_t)b*PDDD + (size_t)pz*PDD + q0;
    u32 AH = base;

    auto copyA = [&](int kd) {
        size_t blk = brow + (size_t)(kd - 1) * PDD - 51;
        for (int i = tid; i < AROWS * 8; i += 256) {
            int r = i >> 3, j = i & 7;
            cp16f(AH + (u32)r*ASTRIDE1 + (u32)j*16,
                  (const char*)(g_xf + (blk + r) * 32) + j*16);
        }
    };
    auto copyB = [&](int g, int s) {
        u32 Bs = base + ASTG1 + (u32)s * BSTG1;
        const char* bsrc = (const char*)(g_w1f + (size_t)(cls*9 + g) * 6144);
        for (int i = tid; i < 1536; i += 256) cp16f(Bs + i*16, bsrc + i*16);
    };

    float acc[4][8][4];
    #pragma unroll
    for (int i = 0; i < 4; i++)
        #pragma unroll
        for (int j = 0; j < 8; j++)
            #pragma unroll
            for (int q = 0; q < 4; q++) acc[i][j][q] = 0.f;

    int arow = wid * 64;
    int lr4 = lane >> 2, lc4 = lane & 3;

    copyA(0); copyB(0, 0); cp_commit();
    for (int g = 0; g < 9; g++) {
        int kd = g / 3, kh = g % 3;
        if (g == 3 || g == 6) {
            __syncthreads();
            copyA(kd); cp_commit();
        }
        cp_wait0();
        __syncthreads();
        if (g + 1 < 9) { copyB(g + 1, (g + 1) & 1); cp_commit(); }

        u32 Bs = base + ASTG1 + (u32)(g & 1) * BSTG1;
        int rowoff = kh * 50;
        u32 abase[4];
        #pragma unroll
        for (int i = 0; i < 4; i++)
            abase[i] = AH + (u32)(arow + 16*i + lr4 + rowoff) * ASTRIDE1 + (u32)lc4 * 4;
        #pragma unroll
        for (int ks = 0; ks < 12; ks++) {
            u32 ro = (u32)(ks >> 2) * ASTRIDE1 + (u32)(ks & 3) * 32;
            u32 a[4][4];
            #pragma unroll
            for (int i = 0; i < 4; i++) {
                lds32(a[i][0], abase[i] + ro);
                lds32(a[i][1], abase[i] + 8*ASTRIDE1 + ro);
                lds32(a[i][2], abase[i] + ro + 16);
                lds32(a[i][3], abase[i] + 8*ASTRIDE1 + ro + 16);
            }
            #pragma unroll
            for (int half = 0; half < 2; half++) {
                u32 bf[4][2];
                #pragma unroll
                for (int nc = 0; nc < 4; nc++)
                    lds64(bf[nc][0], bf[nc][1],
                          Bs + (u32)(((ks*8 + half*4 + nc)*32 + lane)*8));
                #pragma unroll
                for (int i = 0; i < 4; i++)
                    #pragma unroll
                    for (int nc = 0; nc < 4; nc++)
                        mmatf32(acc[i][half*4 + nc], a[i], bf[nc][0], bf[nc][1]);
            }
        }
    }

    // epilogue: bias + relu -> g_af (tf32-rounded fp32, channel-last)
    int qr = lane >> 2, qc = (lane & 3) * 2;
    #pragma unroll
    for (int i = 0; i < 4; i++) {
        #pragma unroll
        for (int rr = 0; rr < 2; rr++) {
            int m = arow + 16*i + 8*rr + qr;
            if (m >= MT) continue;
            int q = q0 + m;
            int py = q / 50, px = q - py * 50;
            if (py < 1 || py > 48 || px < 1 || px > 48) continue;
            size_t lin = (size_t)XOFF + (size_t)b*PDDD + (size_t)pz*PDD + q;
            #pragma unroll
            for (int nc = 0; nc < 8; nc++) {
                int ch = nc*8 + qc;
                float v0 = fmaxf(acc[i][nc][rr*2 + 0] + s_bias[ch],     0.f);
                float v1 = fmaxf(acc[i][nc][rr*2 + 1] + s_bias[ch + 1], 0.f);
                float2 st = make_float2(__uint_as_float(tf32r(v0)),
                                        __uint_as_float(tf32r(v1)));
                *(float2*)(g_af + lin*64 + ch) = st;
            }
        }
    }
}

// ---------------------------------------------------------------------------
// conv2: tf32 64->64 (gamma|beta) + InstanceNorm, 27 taps.
// 256 thr, 8 warps each m64 x n64. A single (620 x 272B), B dbuf 16KB.
// ---------------------------------------------------------------------------
#define ASTG2 (AROWS * ASTRIDE2)
#define C2_DSMEM (ASTG2 + 2*16384)
__global__ __launch_bounds__(256, 1)
void conv2_kernel(const float* __restrict__ x,
                  const float* __restrict__ bg, const float* __restrict__ bb_,
                  const int* __restrict__ ycls, float* __restrict__ out) {
    extern __shared__ char dsm[];
    __shared__ float s_mu[32], s_rs[32], s_bg[32], s_bb[32];

    int tile = blockIdx.x, pz = blockIdx.y + 1, b = blockIdx.z;
    int cls = ycls[b];
    int tid = threadIdx.x, wid = tid >> 5, lane = tid & 31;
    u32 base = (smem_u32(dsm) + 127) & ~127u;
    if (tid < 32) {
        s_mu[tid] = g_mu[b*32 + tid];
        s_rs[tid] = g_rsig[b*32 + tid];
        s_bg[tid] = bg[cls*32 + tid];
        s_bb[tid] = bb_[cls*32 + tid];
    }
    __syncthreads();

    int q0 = tile * MT;
    size_t brow = (size_t)XOFF + (size_t)b*PDDD + (size_t)pz*PDD + q0;
    u32 AH = base;

    auto copyA = [&](int kd) {
        size_t blk = brow + (size_t)(kd - 1) * PDD - 51;
        for (int i = tid; i < AROWS * 16; i += 256) {
            int r = i >> 4, j = i & 15;
            cp16f(AH + (u32)r*ASTRIDE2 + (u32)j*16,
                  (const char*)(g_af + (blk + r) * 64) + j*16);
        }
    };
    auto copyB = [&](int t, int s) {
        u32 Bs = base + ASTG2 + (u32)s * 16384;
        const char* bsrc = (const char*)(g_w2f + (size_t)(cls*27 + t) * 4096);
        for (int i = tid; i < 1024; i += 256) cp16f(Bs + i*16, bsrc + i*16);
    };

    float acc[4][8][4];
    #pragma unroll
    for (int i = 0; i < 4; i++)
        #pragma unroll
        for (int j = 0; j < 8; j++)
            #pragma unroll
            for (int q = 0; q < 4; q++) acc[i][j][q] = 0.f;

    int arow = wid * 64;
    int lr4 = lane >> 2, lc4 = lane & 3;

    copyA(0); copyB(0, 0); cp_commit();
    for (int t = 0; t < 27; t++) {
        int kd = t / 9, kh = (t % 9) / 3, kw = t % 3;
        cp_wait0();
        __syncthreads();
        int nt = t + 1;
        if (nt < 27 && nt % 9 != 0) { copyB(nt, nt & 1); cp_commit(); }
        u32 Bs = base + ASTG2 + (u32)(t & 1) * 16384;
        int rowoff = kh * 50 + kw;
        u32 abase[4];
        #pragma unroll
        for (int i = 0; i < 4; i++)
            abase[i] = AH + (u32)(arow + 16*i + lr4 + rowoff) * ASTRIDE2 + (u32)lc4 * 4;
        #pragma unroll
        for (int ks = 0; ks < 8; ks++) {
            u32 a[4][4];
            #pragma unroll
            for (int i = 0; i < 4; i++) {
                lds32(a[i][0], abase[i] + ks*32);
                lds32(a[i][1], abase[i] + 8*ASTRIDE2 + ks*32);
                lds32(a[i][2], abase[i] + ks*32 + 16);
                lds32(a[i][3], abase[i] + 8*ASTRIDE2 + ks*32 + 16);
            }
            #pragma unroll
            for (int half = 0; half < 2; half++) {
                u32 bf[4][2];
                #pragma unroll
                for (int nc = 0; nc < 4; nc++)
                    lds64(bf[nc][0], bf[nc][1],
                          Bs + (u32)(((ks*8 + half*4 + nc)*32 + lane)*8));
                #pragma unroll
                for (int i = 0; i < 4; i++)
                    #pragma unroll
                    for (int nc = 0; nc < 4; nc++)
                        mmatf32(acc[i][half*4 + nc], a[i], bf[nc][0], bf[nc][1]);
            }
        }
        if (nt < 27 && nt % 9 == 0) {
            __syncthreads();
            copyA(nt / 9); copyB(nt, nt & 1); cp_commit();
        }
    }

    // ---------- exchange epilogue (coalesced output writes) ----------
    __syncthreads();
    float* sg = (float*)(dsm + (base - smem_u32(dsm)));
    float* sb = sg + 512 * 33;

    int qr = lane >> 2, qc = (lane & 3) * 2;
    #pragma unroll
    for (int i = 0; i < 4; i++) {
        #pragma unroll
        for (int rr = 0; rr < 2; rr++) {
            int m = arow + 16*i + 8*rr + qr;
            #pragma unroll
            for (int nc = 0; nc < 8; nc++) {
                int n = nc*8 + qc;
                float v0 = acc[i][nc][rr*2 + 0];
                float v1 = acc[i][nc][rr*2 + 1];
                if (n < 32) { sg[m*33 + n] = v0; sg[m*33 + n + 1] = v1; }
                else        { sb[m*33 + n - 32] = v0; sb[m*33 + n - 31] = v1; }
            }
        }
    }
    __syncthreads();

    for (int m0 = tid; m0 < MT; m0 += 256) {
        int q = q0 + m0;
        int py = q / 50, px = q - py * 50;
        if (py >= 1 && py <= 48 && px >= 1 && px <= 48) {
            size_t sidx = (size_t)b*32*VNNN + (size_t)(pz-1)*VNN + (py-1)*VN + (px-1);
            #pragma unroll 8
            for (int ch = 0; ch < 32; ch++) {
                float gm = sg[m0*33 + ch] + s_bg[ch];
                float bt = sb[m0*33 + ch] + s_bb[ch];
                float xv = x[sidx + (size_t)ch * VNNN];
                out[sidx + (size_t)ch * VNNN] =
                    (xv - s_mu[ch]) * s_rs[ch] * (1.f + gm) + bt;
            }
        }
    }
}

// ---------------------------------------------------------------------------
extern "C" void kernel_launch(void* const* d_in, const int* in_sizes, int n_in,
                              void* d_out, int out_size) {
    const float* x       = (const float*)d_in[0];
    const int*   y       = (const int*)d_in[1];
    const float* Wshared = (const float*)d_in[2];
    const float* bshared = (const float*)d_in[3];
    const float* Wgamma  = (const float*)d_in[4];
    const float* bgamma  = (const float*)d_in[5];
    const float* Wbeta   = (const float*)d_in[6];
    const float* bbeta   = (const float*)d_in[7];
    float* out = (float*)d_out;

    cudaFuncSetAttribute(conv1_kernel, cudaFuncAttributeMaxDynamicSharedMemorySize, C1_DSMEM);
    cudaFuncSetAttribute(conv2_kernel, cudaFuncAttributeMaxDynamicSharedMemorySize, C2_DSMEM);

    stats_kernel<<<NB * 32, 256>>>(x);
    xpose_kernel<<<dim3(PD, NB), 256>>>(x);
    prepb_kernel<<<dim3(27, 8), 256>>>(Wshared, Wgamma, Wbeta);

    conv1_kernel<<<dim3(NTILE, 48, NB), 256, C1_DSMEM>>>(y, bshared);
    conv2_kernel<<<dim3(NTILE, 48, NB), 256, C2_DSMEM>>>(x, bgamma, bbeta, y, out);
}